// round 6
// baseline (speedup 1.0000x reference)
#include <cuda_runtime.h>
#include <cuda_bf16.h>
#include <math.h>
#include <cstdint>

// Problem constants (fixed): N=2048, NF=8, order=16, LMAX=2 => a1=a2=1
constexpr int N = 2048;
constexpr int NF = 8;
constexpr int ORDER = 16;
constexpr int NCOEF = ORDER + 1;          // 17
constexpr size_t NN = (size_t)N * N;      // 4M elems

// Scratch (__device__ globals = sanctioned, no cudaMalloc)
__device__ float         g_Ts[(size_t)NCOEF * NN];   // T_0..T_16 fp32 (272MB)
__device__ __nv_bfloat16 g_hi[(size_t)NCOEF * NN];   // bf16 hi of T_k
__device__ __nv_bfloat16 g_lo[(size_t)NCOEF * NN];   // bf16 lo of T_k
__device__ __nv_bfloat16 g_Fhi[NN];                  // F = 2(L-I), bf16 hi only
__device__ float         g_cw[NCOEF * NF];

// ---------------------------------------------------------------------------
// PTX helpers (arch-neutral sm_80+ only; harness targets plain sm_100)
// ---------------------------------------------------------------------------
__device__ __forceinline__ uint32_t smem_u32(const void* p) {
    uint32_t a;
    asm("{ .reg .u64 t; cvta.to.shared.u64 t, %1; cvt.u32.u64 %0, t; }" : "=r"(a) : "l"(p));
    return a;
}
__device__ __forceinline__ void cp16(uint32_t dst, const void* src) {
    asm volatile("cp.async.cg.shared.global [%0], [%1], 16;" :: "r"(dst), "l"(src));
}
#define CP_COMMIT() asm volatile("cp.async.commit_group;" ::: "memory")

__device__ __forceinline__ void ldsm4(uint32_t (&r)[4], uint32_t addr) {
    asm volatile("ldmatrix.sync.aligned.m8n8.x4.shared.b16 {%0,%1,%2,%3}, [%4];"
                 : "=r"(r[0]), "=r"(r[1]), "=r"(r[2]), "=r"(r[3]) : "r"(addr));
}
// NOTE: non-volatile — pure register op; data deps order it. Lets ptxas
// schedule MMAs into ldsm shadows.
__device__ __forceinline__ void mma_bf16(float (&d)[4], const uint32_t (&a)[4],
                                         uint32_t b0, uint32_t b1) {
    asm("mma.sync.aligned.m16n8k16.row.col.f32.bf16.bf16.f32 "
        "{%0,%1,%2,%3},{%4,%5,%6,%7},{%8,%9},{%0,%1,%2,%3};"
        : "+f"(d[0]), "+f"(d[1]), "+f"(d[2]), "+f"(d[3])
        : "r"(a[0]), "r"(a[1]), "r"(a[2]), "r"(a[3]), "r"(b0), "r"(b1));
}

// 128B XOR swizzle on a 64B-pitch row layout (16B-granular, alignment-safe)
__device__ __forceinline__ uint32_t swz(uint32_t off) {
    return off ^ (((off >> 7) & 7u) << 4);
}

// ---------------------------------------------------------------------------
// Chebyshev coefficients (cw[0] pre-scaled by 0.5)
// ---------------------------------------------------------------------------
__global__ void cheb_coeff(const float* __restrict__ taus, float* __restrict__ cw) {
    int t = threadIdx.x;
    if (t < NCOEF * NF) {
        int k = t >> 3, f = t & 7;
        double tau = (double)taus[f];
        const double PI = 3.14159265358979323846;
        double s = 0.0;
        for (int n = 0; n < NCOEF; n++) {
            double arg = (n + 0.5) / (double)NCOEF;
            s += cos(PI * (double)k * arg) * exp(-(cos(PI * arg) + 1.0) * tau);
        }
        double v = (2.0 / (double)NCOEF) * s;
        if (k == 0) v *= 0.5;
        cw[t] = (float)v;
    }
}

// ---------------------------------------------------------------------------
// Prep: T0=I, T1=L-I (+bf16 split), F=2(L-I) hi only
// ---------------------------------------------------------------------------
__device__ __forceinline__ void split_store(float x, __nv_bfloat16* hi, __nv_bfloat16* lo) {
    __nv_bfloat16 h = __float2bfloat16(x);
    *hi = h;
    *lo = __float2bfloat16(x - __bfloat162float(h));
}

__global__ void __launch_bounds__(256)
cheb_prep(const float* __restrict__ L, float* __restrict__ T0, float* __restrict__ T1,
          __nv_bfloat16* __restrict__ T1hi, __nv_bfloat16* __restrict__ T1lo,
          __nv_bfloat16* __restrict__ Fhi) {
    size_t idx = (size_t)blockIdx.x * 256 + threadIdx.x;   // float4 index
    int i = (int)(idx >> 9);
    int j = ((int)(idx & 511)) << 2;
    size_t off = (size_t)i * N + j;
    float4 l = *(const float4*)(L + off);
    float m[4] = {l.x, l.y, l.z, l.w};
    float t0[4] = {0.f, 0.f, 0.f, 0.f};
#pragma unroll
    for (int c = 0; c < 4; c++)
        if (j + c == i) { m[c] -= 1.0f; t0[c] = 1.0f; }
    *(float4*)(T0 + off) = make_float4(t0[0], t0[1], t0[2], t0[3]);
    *(float4*)(T1 + off) = make_float4(m[0], m[1], m[2], m[3]);
#pragma unroll
    for (int c = 0; c < 4; c++) {
        split_store(m[c], T1hi + off + c, T1lo + off + c);
        Fhi[off + c] = __float2bfloat16(2.0f * m[c]);
    }
}

// ---------------------------------------------------------------------------
// HMMA GEMM step: Tout = Fh @ B - Cold  (2-product: Ah*Bh + Ah*Bl)
// CTA 128x128, 256 thr (8 warps 2x4, warp tile 64x32), BK=32.
// 4-stage cp.async pipeline; batched ldsm per kc + cross-kc A pipelining.
// ---------------------------------------------------------------------------
constexpr uint32_t SZ_A  = 128 * 64;           // 8192 B per operand array
constexpr uint32_t STAGE = 3 * SZ_A;           // Ah, Bh, Bl = 24576
constexpr uint32_t SMEM_GEMM = 4 * STAGE;      // 98304

__global__ void __launch_bounds__(256, 2)
cheb_hmma(const __nv_bfloat16* __restrict__ Ahi_g,
          const __nv_bfloat16* __restrict__ Bhi_g, const __nv_bfloat16* __restrict__ Blo_g,
          const float* __restrict__ Cold, float* __restrict__ Tout,
          __nv_bfloat16* __restrict__ HiOut, __nv_bfloat16* __restrict__ LoOut) {
    extern __shared__ char smem[];
    const uint32_t sb = smem_u32(smem);
    const int tid = threadIdx.x, lane = tid & 31, wid = tid >> 5;
    const int wm = wid >> 2, wn = wid & 3;
    const int row0 = blockIdx.y * 128, col0 = blockIdx.x * 128;

    // producer mapping: thread t handles row t/2, 32B half (t&1); two 16B pieces
    const int prow = tid >> 1;
    const uint32_t pcol = (uint32_t)(tid & 1) * 32;
    const char* gAh = (const char*)Ahi_g + (size_t)(row0 + prow) * 4096 + pcol;
    const char* gBh = (const char*)Bhi_g + (size_t)(col0 + prow) * 4096 + pcol;
    const char* gBl = (const char*)Blo_g + (size_t)(col0 + prow) * 4096 + pcol;
    const uint32_t s0 = swz((uint32_t)prow * 64 + pcol);
    const uint32_t s1 = swz((uint32_t)prow * 64 + pcol + 16);

    auto load_chunk = [&](int stg, int ch) {
        const uint32_t base = sb + (uint32_t)stg * STAGE;
        const uint32_t go = (uint32_t)ch * 64;
        cp16(base + s0,              gAh + go);
        cp16(base + s1,              gAh + go + 16);
        cp16(base + SZ_A + s0,       gBh + go);
        cp16(base + SZ_A + s1,       gBh + go + 16);
        cp16(base + 2 * SZ_A + s0,   gBl + go);
        cp16(base + 2 * SZ_A + s1,   gBl + go + 16);
        CP_COMMIT();
    };

    float acc[4][4][4];
#pragma unroll
    for (int i = 0; i < 4; i++)
#pragma unroll
        for (int j = 0; j < 4; j++)
#pragma unroll
            for (int r = 0; r < 4; r++) acc[i][j][r] = 0.f;

    // ldmatrix lane offsets (row within 16-row tile, 16B column select)
    const uint32_t arow = (uint32_t)((lane & 7) + ((lane >> 3) & 1) * 8);
    const uint32_t acol = (uint32_t)(lane >> 4) * 16;
    const uint32_t brow = (uint32_t)((lane & 7) + ((lane >> 4) & 1) * 8);
    const uint32_t bcol = (uint32_t)((lane >> 3) & 1) * 16;

    load_chunk(0, 0);
    load_chunk(1, 1);
    load_chunk(2, 2);

    // MMA sweep over one kc: 16 hh then 16 hl, same-acc dep distance = 16
    auto mma_kc = [&](const uint32_t (&a)[4][4], const uint32_t (&bh)[2][4],
                      const uint32_t (&bl)[2][4]) {
#pragma unroll
        for (int bt = 0; bt < 2; bt++)
#pragma unroll
            for (int mt = 0; mt < 4; mt++) {
                mma_bf16(acc[mt][2 * bt],     a[mt], bh[bt][0], bh[bt][1]);
                mma_bf16(acc[mt][2 * bt + 1], a[mt], bh[bt][2], bh[bt][3]);
            }
#pragma unroll
        for (int bt = 0; bt < 2; bt++)
#pragma unroll
            for (int mt = 0; mt < 4; mt++) {
                mma_bf16(acc[mt][2 * bt],     a[mt], bl[bt][0], bl[bt][1]);
                mma_bf16(acc[mt][2 * bt + 1], a[mt], bl[bt][2], bl[bt][3]);
            }
    };

    constexpr int NCH = N / 32;   // 64
    for (int ch = 0; ch < NCH; ch++) {
        const int stg = ch & 3;
        const int rem = NCH - 1 - ch;
        if (rem >= 2)      asm volatile("cp.async.wait_group 2;" ::: "memory");
        else if (rem == 1) asm volatile("cp.async.wait_group 1;" ::: "memory");
        else               asm volatile("cp.async.wait_group 0;" ::: "memory");
        __syncthreads();
        if (ch + 3 < NCH) load_chunk((ch + 3) & 3, ch + 3);   // overlap with MMAs

        const uint32_t base = sb + (uint32_t)stg * STAGE;

        uint32_t a0[4][4], a1[4][4], bh[2][4], bl[2][4];
        // --- kc0: batch-load all fragments, plus kc1's A fragments ---------
#pragma unroll
        for (int mt = 0; mt < 4; mt++) {
            const uint32_t off = ((uint32_t)(wm * 64 + mt * 16) + arow) * 64 + acol;
            ldsm4(a0[mt], base + swz(off));
        }
#pragma unroll
        for (int bt = 0; bt < 2; bt++) {
            const uint32_t offb = ((uint32_t)(wn * 32 + bt * 16) + brow) * 64 + bcol;
            ldsm4(bh[bt], base + SZ_A + swz(offb));
            ldsm4(bl[bt], base + 2 * SZ_A + swz(offb));
        }
#pragma unroll
        for (int mt = 0; mt < 4; mt++) {
            const uint32_t off = ((uint32_t)(wm * 64 + mt * 16) + arow) * 64 + 32 + acol;
            ldsm4(a1[mt], base + swz(off));
        }
        mma_kc(a0, bh, bl);

        // --- kc1: only B fragments remain to load --------------------------
#pragma unroll
        for (int bt = 0; bt < 2; bt++) {
            const uint32_t offb = ((uint32_t)(wn * 32 + bt * 16) + brow) * 64 + 32 + bcol;
            ldsm4(bh[bt], base + SZ_A + swz(offb));
            ldsm4(bl[bt], base + 2 * SZ_A + swz(offb));
        }
        mma_kc(a1, bh, bl);
    }

    // Epilogue: v = acc - Cold; write fp32 + bf16 hi/lo split for next step
#pragma unroll
    for (int mt = 0; mt < 4; mt++) {
        const int r = row0 + wm * 64 + mt * 16 + (lane >> 2);
#pragma unroll
        for (int nt = 0; nt < 4; nt++) {
            const int c = col0 + wn * 32 + nt * 8 + (lane & 3) * 2;
            const size_t o0 = (size_t)r * N + c;
            const size_t o1 = o0 + (size_t)8 * N;
            const float2 c0 = *(const float2*)(Cold + o0);
            const float2 c1 = *(const float2*)(Cold + o1);
            const float v0 = acc[mt][nt][0] - c0.x;
            const float v1 = acc[mt][nt][1] - c0.y;
            const float v2 = acc[mt][nt][2] - c1.x;
            const float v3 = acc[mt][nt][3] - c1.y;
            *(float2*)(Tout + o0) = make_float2(v0, v1);
            *(float2*)(Tout + o1) = make_float2(v2, v3);
            const __nv_bfloat16 h0 = __float2bfloat16(v0), h1 = __float2bfloat16(v1);
            const __nv_bfloat16 h2 = __float2bfloat16(v2), h3 = __float2bfloat16(v3);
            *(__nv_bfloat162*)(HiOut + o0) = __halves2bfloat162(h0, h1);
            *(__nv_bfloat162*)(HiOut + o1) = __halves2bfloat162(h2, h3);
            *(__nv_bfloat162*)(LoOut + o0) = __halves2bfloat162(
                __float2bfloat16(v0 - __bfloat162float(h0)),
                __float2bfloat16(v1 - __bfloat162float(h1)));
            *(__nv_bfloat162*)(LoOut + o1) = __halves2bfloat162(
                __float2bfloat16(v2 - __bfloat162float(h2)),
                __float2bfloat16(v3 - __bfloat162float(h3)));
        }
    }
}

// ---------------------------------------------------------------------------
// Finalize: out[f*N+i][j] = sum_k cw[k][f] * T_k[i][j]
// ---------------------------------------------------------------------------
__global__ void __launch_bounds__(256)
cheb_finalize(const float* __restrict__ Ts, const float* __restrict__ cw,
              float* __restrict__ out) {
    __shared__ float cws[NCOEF * NF];
    if (threadIdx.x < NCOEF * NF) cws[threadIdx.x] = cw[threadIdx.x];
    __syncthreads();

    size_t idx = (size_t)blockIdx.x * 256 + threadIdx.x;
    int i = (int)(idx >> 9);
    int j = ((int)(idx & 511)) << 2;
    size_t off = (size_t)i * N + j;

    float4 t[NCOEF];
#pragma unroll
    for (int k = 0; k < NCOEF; k++)
        t[k] = *(const float4*)(Ts + (size_t)k * NN + off);

#pragma unroll
    for (int f = 0; f < NF; f++) {
        float4 s = make_float4(0.f, 0.f, 0.f, 0.f);
#pragma unroll
        for (int k = 0; k < NCOEF; k++) {
            float c = cws[k * NF + f];
            s.x += c * t[k].x; s.y += c * t[k].y;
            s.z += c * t[k].z; s.w += c * t[k].w;
        }
        *(float4*)(out + (size_t)f * NN + off) = s;
    }
}

// ---------------------------------------------------------------------------
// Launch (graph-capturable, allocation-free)
// ---------------------------------------------------------------------------
extern "C" void kernel_launch(void* const* d_in, const int* in_sizes, int n_in,
                              void* d_out, int out_size) {
    const float* L    = (const float*)d_in[0];
    const float* taus = (const float*)d_in[1];
    float* out = (float*)d_out;

    float *Ts, *cw;
    __nv_bfloat16 *hi, *lo, *Fhi;
    cudaGetSymbolAddress((void**)&Ts, g_Ts);
    cudaGetSymbolAddress((void**)&cw, g_cw);
    cudaGetSymbolAddress((void**)&hi, g_hi);
    cudaGetSymbolAddress((void**)&lo, g_lo);
    cudaGetSymbolAddress((void**)&Fhi, g_Fhi);

    cudaFuncSetAttribute(cheb_hmma, cudaFuncAttributeMaxDynamicSharedMemorySize,
                         SMEM_GEMM);

    cheb_coeff<<<1, 160>>>(taus, cw);
    cheb_prep<<<(int)(NN / 4 / 256), 256>>>(L, Ts, Ts + NN, hi + NN, lo + NN, Fhi);

    dim3 grid(N / 128, N / 128), block(256);
    for (int k = 2; k <= ORDER; k++) {
        cheb_hmma<<<grid, block, SMEM_GEMM>>>(
            Fhi,
            hi + (size_t)(k - 1) * NN, lo + (size_t)(k - 1) * NN,   // B = T_{k-1}
            Ts + (size_t)(k - 2) * NN,                              // Cold = T_{k-2}
            Ts + (size_t)k * NN,                                    // T_k fp32
            hi + (size_t)k * NN, lo + (size_t)k * NN);              // T_k split
    }
    cheb_finalize<<<(int)(NN / 4 / 256), 256>>>(Ts, cw, out);
}

// round 7
// speedup vs baseline: 1.5717x; 1.5717x over previous
#include <cuda_runtime.h>
#include <cuda_bf16.h>
#include <math.h>
#include <cstdint>

// Problem constants (fixed): N=2048, NF=8, order=16, LMAX=2 => a1=a2=1
constexpr int N = 2048;
constexpr int NF = 8;
constexpr int ORDER = 16;
constexpr int NCOEF = ORDER + 1;          // 17
constexpr size_t NN = (size_t)N * N;      // 4M elems

// Scratch (__device__ globals = sanctioned, no cudaMalloc)
__device__ float         g_Ts[(size_t)NCOEF * NN];   // T_0..T_16 fp32 (272MB)
__device__ __nv_bfloat16 g_hi[(size_t)NCOEF * NN];   // bf16 hi of T_k
__device__ __nv_bfloat16 g_lo[(size_t)NCOEF * NN];   // bf16 lo of T_k
__device__ __nv_bfloat16 g_Fhi[NN];                  // F = 2(L-I), bf16 hi only
__device__ float         g_cw[NCOEF * NF];

// ---------------------------------------------------------------------------
// PTX helpers (arch-neutral sm_80+ only; harness targets plain sm_100)
// ---------------------------------------------------------------------------
__device__ __forceinline__ uint32_t smem_u32(const void* p) {
    uint32_t a;
    asm("{ .reg .u64 t; cvta.to.shared.u64 t, %1; cvt.u32.u64 %0, t; }" : "=r"(a) : "l"(p));
    return a;
}
__device__ __forceinline__ void cp16(uint32_t dst, const void* src) {
    asm volatile("cp.async.cg.shared.global [%0], [%1], 16;" :: "r"(dst), "l"(src));
}
#define CP_COMMIT() asm volatile("cp.async.commit_group;" ::: "memory")

__device__ __forceinline__ void ldsm4(uint32_t (&r)[4], uint32_t addr) {
    asm volatile("ldmatrix.sync.aligned.m8n8.x4.shared.b16 {%0,%1,%2,%3}, [%4];"
                 : "=r"(r[0]), "=r"(r[1]), "=r"(r[2]), "=r"(r[3]) : "r"(addr));
}
__device__ __forceinline__ void mma_bf16(float (&d)[4], const uint32_t (&a)[4],
                                         uint32_t b0, uint32_t b1) {
    asm("mma.sync.aligned.m16n8k16.row.col.f32.bf16.bf16.f32 "
        "{%0,%1,%2,%3},{%4,%5,%6,%7},{%8,%9},{%0,%1,%2,%3};"
        : "+f"(d[0]), "+f"(d[1]), "+f"(d[2]), "+f"(d[3])
        : "r"(a[0]), "r"(a[1]), "r"(a[2]), "r"(a[3]), "r"(b0), "r"(b1));
}

// 128B XOR swizzle on a 64B-pitch row layout (16B-granular, alignment-safe)
__device__ __forceinline__ uint32_t swz(uint32_t off) {
    return off ^ (((off >> 7) & 7u) << 4);
}

// ---------------------------------------------------------------------------
// Chebyshev coefficients (cw[0] pre-scaled by 0.5)
// ---------------------------------------------------------------------------
__global__ void cheb_coeff(const float* __restrict__ taus, float* __restrict__ cw) {
    int t = threadIdx.x;
    if (t < NCOEF * NF) {
        int k = t >> 3, f = t & 7;
        double tau = (double)taus[f];
        const double PI = 3.14159265358979323846;
        double s = 0.0;
        for (int n = 0; n < NCOEF; n++) {
            double arg = (n + 0.5) / (double)NCOEF;
            s += cos(PI * (double)k * arg) * exp(-(cos(PI * arg) + 1.0) * tau);
        }
        double v = (2.0 / (double)NCOEF) * s;
        if (k == 0) v *= 0.5;
        cw[t] = (float)v;
    }
}

// ---------------------------------------------------------------------------
// Prep: T0=I, T1=L-I (+bf16 split), F=2(L-I) hi only
// ---------------------------------------------------------------------------
__device__ __forceinline__ void split_store(float x, __nv_bfloat16* hi, __nv_bfloat16* lo) {
    __nv_bfloat16 h = __float2bfloat16(x);
    *hi = h;
    *lo = __float2bfloat16(x - __bfloat162float(h));
}

__global__ void __launch_bounds__(256)
cheb_prep(const float* __restrict__ L, float* __restrict__ T0, float* __restrict__ T1,
          __nv_bfloat16* __restrict__ T1hi, __nv_bfloat16* __restrict__ T1lo,
          __nv_bfloat16* __restrict__ Fhi) {
    size_t idx = (size_t)blockIdx.x * 256 + threadIdx.x;   // float4 index
    int i = (int)(idx >> 9);
    int j = ((int)(idx & 511)) << 2;
    size_t off = (size_t)i * N + j;
    float4 l = *(const float4*)(L + off);
    float m[4] = {l.x, l.y, l.z, l.w};
    float t0[4] = {0.f, 0.f, 0.f, 0.f};
#pragma unroll
    for (int c = 0; c < 4; c++)
        if (j + c == i) { m[c] -= 1.0f; t0[c] = 1.0f; }
    *(float4*)(T0 + off) = make_float4(t0[0], t0[1], t0[2], t0[3]);
    *(float4*)(T1 + off) = make_float4(m[0], m[1], m[2], m[3]);
#pragma unroll
    for (int c = 0; c < 4; c++) {
        split_store(m[c], T1hi + off + c, T1lo + off + c);
        Fhi[off + c] = __float2bfloat16(2.0f * m[c]);
    }
}

// ---------------------------------------------------------------------------
// HMMA GEMM step (TRIANGULAR): Tout = Fh @ B - Cold, lower-triangle tiles only.
// Off-diagonal tiles also write the mirrored (transposed) tile — output is
// symmetric, so 136 of 256 tiles cover everything (1.88x fewer HMMAs).
// CTA 128x128, 256 thr (8 warps 2x4, warp tile 64x32), BK=32, 4-stage cp.async.
// ---------------------------------------------------------------------------
constexpr uint32_t SZ_A  = 128 * 64;           // 8192 B per operand array
constexpr uint32_t STAGE = 3 * SZ_A;           // Ah, Bh, Bl = 24576
constexpr uint32_t SMEM_GEMM = 4 * STAGE;      // 98304 (also covers 128x129 f32)
constexpr int NTILE = 16;                      // 2048/128
constexpr int NTRI = NTILE * (NTILE + 1) / 2;  // 136

__global__ void __launch_bounds__(256, 2)
cheb_hmma(const __nv_bfloat16* __restrict__ Ahi_g,
          const __nv_bfloat16* __restrict__ Bhi_g, const __nv_bfloat16* __restrict__ Blo_g,
          const float* __restrict__ Cold, float* __restrict__ Tout,
          __nv_bfloat16* __restrict__ HiOut, __nv_bfloat16* __restrict__ LoOut) {
    extern __shared__ char smem[];
    const uint32_t sb = smem_u32(smem);
    const int tid = threadIdx.x, lane = tid & 31, wid = tid >> 5;
    const int wm = wid >> 2, wn = wid & 3;

    // Triangular unrank: blockIdx.x -> (by, bx) with by >= bx
    int by = (int)((sqrtf(8.0f * (float)blockIdx.x + 1.0f) - 1.0f) * 0.5f);
    while ((by + 1) * (by + 2) / 2 <= (int)blockIdx.x) by++;
    while (by * (by + 1) / 2 > (int)blockIdx.x) by--;
    const int bx = (int)blockIdx.x - by * (by + 1) / 2;
    const int row0 = by * 128, col0 = bx * 128;
    const bool mirror = (bx != by);

    // producer mapping: thread t handles row t/2, 32B half (t&1); two 16B pieces
    const int prow = tid >> 1;
    const uint32_t pcol = (uint32_t)(tid & 1) * 32;
    const char* gAh = (const char*)Ahi_g + (size_t)(row0 + prow) * 4096 + pcol;
    const char* gBh = (const char*)Bhi_g + (size_t)(col0 + prow) * 4096 + pcol;
    const char* gBl = (const char*)Blo_g + (size_t)(col0 + prow) * 4096 + pcol;
    const uint32_t s0 = swz((uint32_t)prow * 64 + pcol);
    const uint32_t s1 = swz((uint32_t)prow * 64 + pcol + 16);

    auto load_chunk = [&](int stg, int ch) {
        const uint32_t base = sb + (uint32_t)stg * STAGE;
        const uint32_t go = (uint32_t)ch * 64;
        cp16(base + s0,              gAh + go);
        cp16(base + s1,              gAh + go + 16);
        cp16(base + SZ_A + s0,       gBh + go);
        cp16(base + SZ_A + s1,       gBh + go + 16);
        cp16(base + 2 * SZ_A + s0,   gBl + go);
        cp16(base + 2 * SZ_A + s1,   gBl + go + 16);
        CP_COMMIT();
    };

    float acc[4][4][4];
#pragma unroll
    for (int i = 0; i < 4; i++)
#pragma unroll
        for (int j = 0; j < 4; j++)
#pragma unroll
            for (int r = 0; r < 4; r++) acc[i][j][r] = 0.f;

    const uint32_t arow = (uint32_t)((lane & 7) + ((lane >> 3) & 1) * 8);
    const uint32_t acol = (uint32_t)(lane >> 4) * 16;
    const uint32_t brow = (uint32_t)((lane & 7) + ((lane >> 4) & 1) * 8);
    const uint32_t bcol = (uint32_t)((lane >> 3) & 1) * 16;

    load_chunk(0, 0);
    load_chunk(1, 1);
    load_chunk(2, 2);

    auto mma_kc = [&](const uint32_t (&a)[4][4], const uint32_t (&bh)[2][4],
                      const uint32_t (&bl)[2][4]) {
#pragma unroll
        for (int bt = 0; bt < 2; bt++)
#pragma unroll
            for (int mt = 0; mt < 4; mt++) {
                mma_bf16(acc[mt][2 * bt],     a[mt], bh[bt][0], bh[bt][1]);
                mma_bf16(acc[mt][2 * bt + 1], a[mt], bh[bt][2], bh[bt][3]);
            }
#pragma unroll
        for (int bt = 0; bt < 2; bt++)
#pragma unroll
            for (int mt = 0; mt < 4; mt++) {
                mma_bf16(acc[mt][2 * bt],     a[mt], bl[bt][0], bl[bt][1]);
                mma_bf16(acc[mt][2 * bt + 1], a[mt], bl[bt][2], bl[bt][3]);
            }
    };

    constexpr int NCH = N / 32;   // 64
    for (int ch = 0; ch < NCH; ch++) {
        const int stg = ch & 3;
        const int rem = NCH - 1 - ch;
        if (rem >= 2)      asm volatile("cp.async.wait_group 2;" ::: "memory");
        else if (rem == 1) asm volatile("cp.async.wait_group 1;" ::: "memory");
        else               asm volatile("cp.async.wait_group 0;" ::: "memory");
        __syncthreads();
        if (ch + 3 < NCH) load_chunk((ch + 3) & 3, ch + 3);

        const uint32_t base = sb + (uint32_t)stg * STAGE;
        uint32_t a0[4][4], a1[4][4], bh[2][4], bl[2][4];
#pragma unroll
        for (int mt = 0; mt < 4; mt++) {
            const uint32_t off = ((uint32_t)(wm * 64 + mt * 16) + arow) * 64 + acol;
            ldsm4(a0[mt], base + swz(off));
        }
#pragma unroll
        for (int bt = 0; bt < 2; bt++) {
            const uint32_t offb = ((uint32_t)(wn * 32 + bt * 16) + brow) * 64 + bcol;
            ldsm4(bh[bt], base + SZ_A + swz(offb));
            ldsm4(bl[bt], base + 2 * SZ_A + swz(offb));
        }
#pragma unroll
        for (int mt = 0; mt < 4; mt++) {
            const uint32_t off = ((uint32_t)(wm * 64 + mt * 16) + arow) * 64 + 32 + acol;
            ldsm4(a1[mt], base + swz(off));
        }
        mma_kc(a0, bh, bl);
#pragma unroll
        for (int bt = 0; bt < 2; bt++) {
            const uint32_t offb = ((uint32_t)(wn * 32 + bt * 16) + brow) * 64 + 32 + bcol;
            ldsm4(bh[bt], base + SZ_A + swz(offb));
            ldsm4(bl[bt], base + 2 * SZ_A + swz(offb));
        }
        mma_kc(a1, bh, bl);
    }

    // -------- direct epilogue: v = acc - Cold; also stage v in smem --------
    __syncthreads();   // all warps done with pipeline stages; smem reused below
    float* ts = (float*)smem;   // 128 x 128 tile, pitch 129 floats (66048 B)

#pragma unroll
    for (int mt = 0; mt < 4; mt++) {
        const int rl = wm * 64 + mt * 16 + (lane >> 2);
        const int r = row0 + rl;
#pragma unroll
        for (int nt = 0; nt < 4; nt++) {
            const int cl = wn * 32 + nt * 8 + (lane & 3) * 2;
            const int c = col0 + cl;
            const size_t o0 = (size_t)r * N + c;
            const size_t o1 = o0 + (size_t)8 * N;
            const float2 c0 = *(const float2*)(Cold + o0);
            const float2 c1 = *(const float2*)(Cold + o1);
            const float v0 = acc[mt][nt][0] - c0.x;
            const float v1 = acc[mt][nt][1] - c0.y;
            const float v2 = acc[mt][nt][2] - c1.x;
            const float v3 = acc[mt][nt][3] - c1.y;
            *(float2*)(Tout + o0) = make_float2(v0, v1);
            *(float2*)(Tout + o1) = make_float2(v2, v3);
            const __nv_bfloat16 h0 = __float2bfloat16(v0), h1 = __float2bfloat16(v1);
            const __nv_bfloat16 h2 = __float2bfloat16(v2), h3 = __float2bfloat16(v3);
            *(__nv_bfloat162*)(HiOut + o0) = __halves2bfloat162(h0, h1);
            *(__nv_bfloat162*)(HiOut + o1) = __halves2bfloat162(h2, h3);
            *(__nv_bfloat162*)(LoOut + o0) = __halves2bfloat162(
                __float2bfloat16(v0 - __bfloat162float(h0)),
                __float2bfloat16(v1 - __bfloat162float(h1)));
            *(__nv_bfloat162*)(LoOut + o1) = __halves2bfloat162(
                __float2bfloat16(v2 - __bfloat162float(h2)),
                __float2bfloat16(v3 - __bfloat162float(h3)));
            if (mirror) {
                ts[rl * 129 + cl]           = v0;
                ts[rl * 129 + cl + 1]       = v1;
                ts[(rl + 8) * 129 + cl]     = v2;
                ts[(rl + 8) * 129 + cl + 1] = v3;
            }
        }
    }

    // -------- mirror epilogue: write transposed tile (coalesced) -----------
    if (mirror) {
        __syncthreads();
#pragma unroll 1
        for (int it = 0; it < 16; it++) {
            const int cr = (tid >> 5) + it * 8;          // local col of tile = row of mirror
            const size_t orow = (size_t)(col0 + cr) * N + row0;
#pragma unroll
            for (int q = 0; q < 4; q++) {
                const int rr = lane + q * 32;
                const float v = ts[rr * 129 + cr];       // conflict-free (129 odd)
                Tout[orow + rr] = v;
                const __nv_bfloat16 h = __float2bfloat16(v);
                HiOut[orow + rr] = h;
                LoOut[orow + rr] = __float2bfloat16(v - __bfloat162float(h));
            }
        }
    }
}

// ---------------------------------------------------------------------------
// Finalize: out[f*N+i][j] = sum_k cw[k][f] * T_k[i][j]
// ---------------------------------------------------------------------------
__global__ void __launch_bounds__(256)
cheb_finalize(const float* __restrict__ Ts, const float* __restrict__ cw,
              float* __restrict__ out) {
    __shared__ float cws[NCOEF * NF];
    if (threadIdx.x < NCOEF * NF) cws[threadIdx.x] = cw[threadIdx.x];
    __syncthreads();

    size_t idx = (size_t)blockIdx.x * 256 + threadIdx.x;
    int i = (int)(idx >> 9);
    int j = ((int)(idx & 511)) << 2;
    size_t off = (size_t)i * N + j;

    float4 t[NCOEF];
#pragma unroll
    for (int k = 0; k < NCOEF; k++)
        t[k] = *(const float4*)(Ts + (size_t)k * NN + off);

#pragma unroll
    for (int f = 0; f < NF; f++) {
        float4 s = make_float4(0.f, 0.f, 0.f, 0.f);
#pragma unroll
        for (int k = 0; k < NCOEF; k++) {
            float c = cws[k * NF + f];
            s.x += c * t[k].x; s.y += c * t[k].y;
            s.z += c * t[k].z; s.w += c * t[k].w;
        }
        *(float4*)(out + (size_t)f * NN + off) = s;
    }
}

// ---------------------------------------------------------------------------
// Launch (graph-capturable, allocation-free)
// ---------------------------------------------------------------------------
extern "C" void kernel_launch(void* const* d_in, const int* in_sizes, int n_in,
                              void* d_out, int out_size) {
    const float* L    = (const float*)d_in[0];
    const float* taus = (const float*)d_in[1];
    float* out = (float*)d_out;

    float *Ts, *cw;
    __nv_bfloat16 *hi, *lo, *Fhi;
    cudaGetSymbolAddress((void**)&Ts, g_Ts);
    cudaGetSymbolAddress((void**)&cw, g_cw);
    cudaGetSymbolAddress((void**)&hi, g_hi);
    cudaGetSymbolAddress((void**)&lo, g_lo);
    cudaGetSymbolAddress((void**)&Fhi, g_Fhi);

    cudaFuncSetAttribute(cheb_hmma, cudaFuncAttributeMaxDynamicSharedMemorySize,
                         SMEM_GEMM);

    cheb_coeff<<<1, 160>>>(taus, cw);
    cheb_prep<<<(int)(NN / 4 / 256), 256>>>(L, Ts, Ts + NN, hi + NN, lo + NN, Fhi);

    for (int k = 2; k <= ORDER; k++) {
        cheb_hmma<<<NTRI, 256, SMEM_GEMM>>>(
            Fhi,
            hi + (size_t)(k - 1) * NN, lo + (size_t)(k - 1) * NN,   // B = T_{k-1}
            Ts + (size_t)(k - 2) * NN,                              // Cold = T_{k-2}
            Ts + (size_t)k * NN,                                    // T_k fp32
            hi + (size_t)k * NN, lo + (size_t)k * NN);              // T_k split
    }
    cheb_finalize<<<(int)(NN / 4 / 256), 256>>>(Ts, cw, out);
}